// round 15
// baseline (speedup 1.0000x reference)
#include <cuda_runtime.h>
#include <cuda_fp16.h>

#define BB 256
#define TT 2048
#define HH 64
#define NCHUNK (TT / 32)

// scratch for per-(dir,b,t) fc dot products: 4 MB
__device__ float g_dot[2 * BB * TT];

typedef unsigned long long ull;

__device__ __forceinline__ ull pack2(float lo, float hi) {
    ull r; asm("mov.b64 %0, {%1, %2};" : "=l"(r) : "f"(lo), "f"(hi)); return r;
}
__device__ __forceinline__ void unpack2(ull v, float& lo, float& hi) {
    asm("mov.b64 {%0, %1}, %2;" : "=f"(lo), "=f"(hi) : "l"(v));
}
__device__ __forceinline__ ull fma2(ull a, ull b, ull c) {
    ull d; asm("fma.rn.f32x2 %0, %1, %2, %3;" : "=l"(d) : "l"(a), "l"(b), "l"(c)); return d;
}
__device__ __forceinline__ ull add2(ull a, ull b) {
    ull d; asm("add.rn.f32x2 %0, %1, %2;" : "=l"(d) : "l"(a), "l"(b)); return d;
}
__device__ __forceinline__ float tanh_fast(float z) {
    float r; asm("tanh.approx.f32 %0, %1;" : "=f"(r) : "f"(z)); return r;
}
__device__ __forceinline__ __half2 u2h2(unsigned int u) {
    return *reinterpret_cast<__half2*>(&u);
}
// compiler-only ordering fence
__device__ __forceinline__ void cbar() { asm volatile("" ::: "memory"); }

__global__ __launch_bounds__(128, 1) void birnn_main(
    const float* __restrict__ x,
    const float* __restrict__ w_ih_f, const float* __restrict__ w_hh_f,
    const float* __restrict__ b_ih_f, const float* __restrict__ b_hh_f,
    const float* __restrict__ w_ih_b, const float* __restrict__ w_hh_b,
    const float* __restrict__ b_ih_b, const float* __restrict__ b_hh_b,
    const float* __restrict__ w_fc,
    float* __restrict__ out)
{
    // fp16 h broadcast buffer (consumers read rows 16..63; all 64 rows written
    // branchlessly). fp32 rows 0..15 travel by SHUFFLE: the ull multiplicand
    // for k-pair m is exactly lane m's packed (h0,h1).
    __shared__ __align__(16) __half hbuf16[4][2][HH];
    __shared__ float pbuf[4][32 * 33];   // per-warp fc-dot partials (padded)

    const int wid  = threadIdx.x >> 5;
    const int lane = threadIdx.x & 31;
    const int chain = blockIdx.x * 4 + wid;   // 0..511
    const int dir = chain >> 8;               // 0 = fwd, 1 = bwd
    const int b   = chain & 255;

    const float* wih = dir ? w_ih_b : w_ih_f;
    const float* whh = dir ? w_hh_b : w_hh_f;
    const float* bih = dir ? b_ih_b : b_ih_f;
    const float* bhh = dir ? b_hh_b : b_hh_f;

    const int r0 = 2 * lane, r1 = 2 * lane + 1;   // rows owned by this thread

    // --- recurrent weights, k-split 16/48 (same arithmetic as R12) ---
    // fp32 part (k = 0..15), k-paired f32x2
    ull wa32[8], wb32[8];
    // fp16 part (k = 16..63), k-paired half2
    __half2 wa16[24], wb16[24];
    {
        const float* rowA = whh + r0 * HH;
        const float* rowB = whh + r1 * HH;
        const ull* rowAu = reinterpret_cast<const ull*>(rowA);
        const ull* rowBu = reinterpret_cast<const ull*>(rowB);
#pragma unroll
        for (int m = 0; m < 8; m++) { wa32[m] = rowAu[m]; wb32[m] = rowBu[m]; }
#pragma unroll
        for (int m = 0; m < 24; m++) {
            wa16[m] = __floats2half2_rn(rowA[16 + 2 * m], rowA[17 + 2 * m]);
            wb16[m] = __floats2half2_rn(rowB[16 + 2 * m], rowB[17 + 2 * m]);
        }
    }
    const float wihA = wih[r0], wihB = wih[r1];
    const float biasA = bih[r0] + bhh[r0], biasB = bih[r1] + bhh[r1];
    const float wfa = w_fc[r0], wfb = w_fc[r1];

    // h = 0 into phase 0 (fp16 buffer) and register pack
    reinterpret_cast<unsigned int*>(&hbuf16[wid][0][0])[lane] = 0u;
    cbar();

    float h0 = 0.f, h1 = 0.f;
    ull hpack = 0;                      // packed (h0, h1), shuffled by consumers
    const float* xb = x + b * TT;
    const __half2 z16 = __floats2half2_rn(0.f, 0.f);

    // prefetch x for chunk 0
    float xcur = xb[dir ? (TT - 32 + lane) : lane];

    for (int chunk = 0; chunk < NCHUNK; chunk++) {
        const int tb = dir ? (TT - 1 - chunk * 32) : (chunk * 32);
        int nc = (chunk + 1 < NCHUNK) ? (chunk + 1) : chunk;
        float xnext = xb[dir ? (TT - 1 - nc * 32 - 31 + lane) : (nc * 32 + lane)];

#define STEP(SS, RD, WR)                                                          \
        {                                                                         \
            const int s = (SS);                                                   \
            float xs = __shfl_sync(0xffffffffu, xcur, dir ? (31 - s) : s);        \
            /* init folded into fp32 accumulator lane 0 */                        \
            ull a0 = pack2(fmaf(xs, wihA, biasA), 0.f);                           \
            ull c0 = pack2(fmaf(xs, wihB, biasB), 0.f);                           \
            ull a1 = 0, c1 = 0;                                                   \
            __half2 p0A = z16, p1A = z16, p0B = z16, p1B = z16;                   \
            const uint4* h16 =                                                    \
                reinterpret_cast<const uint4*>(&hbuf16[wid][RD][16]);             \
            /* fp32 MAC block via SHUFFLE: multiplicand for k-pair m is lane */   \
            /* m's hpack. shfls issue into the tanh-wait bubble; no STS/LDS. */   \
            _Pragma("unroll")                                                     \
            for (int m = 0; m < 8; m += 2) {                                      \
                ull v0 = __shfl_sync(0xffffffffu, hpack, m);                      \
                ull v1 = __shfl_sync(0xffffffffu, hpack, m + 1);                  \
                a0 = fma2(wa32[m],     v0, a0);                                   \
                c0 = fma2(wb32[m],     v0, c0);                                   \
                a1 = fma2(wa32[m + 1], v1, a1);                                   \
                c1 = fma2(wb32[m + 1], v1, c1);                                   \
            }                                                                     \
            /* fp16 MAC block second: cvt+store latency covered by fp32 block */  \
            _Pragma("unroll")                                                     \
            for (int k = 0; k < 6; k++) {                                         \
                uint4 v = h16[k];                                                 \
                __half2 q0 = u2h2(v.x), q1 = u2h2(v.y);                           \
                __half2 q2 = u2h2(v.z), q3 = u2h2(v.w);                           \
                p0A = __hfma2(wa16[4 * k + 0], q0, p0A);                          \
                p0B = __hfma2(wb16[4 * k + 0], q0, p0B);                          \
                p1A = __hfma2(wa16[4 * k + 1], q1, p1A);                          \
                p1B = __hfma2(wb16[4 * k + 1], q1, p1B);                          \
                p0A = __hfma2(wa16[4 * k + 2], q2, p0A);                          \
                p0B = __hfma2(wb16[4 * k + 2], q2, p0B);                          \
                p1A = __hfma2(wa16[4 * k + 3], q3, p1A);                          \
                p1B = __hfma2(wb16[4 * k + 3], q3, p1B);                          \
            }                                                                     \
            /* fp16 partials -> fp32 BEFORE any full-magnitude add */             \
            float2 qA = __half22float2(__hadd2(p0A, p1A));                        \
            float2 qB = __half22float2(__hadd2(p0B, p1B));                        \
            ull sA = add2(a0, a1);                                                \
            ull sB = add2(c0, c1);                                                \
            float lA, hA, lB, hB;                                                 \
            unpack2(sA, lA, hA);                                                  \
            unpack2(sB, lB, hB);                                                  \
            h0 = tanh_fast((lA + hA) + (qA.x + qA.y));                            \
            h1 = tanh_fast((lB + hB) + (qB.x + qB.y));                            \
            hpack = pack2(h0, h1);                                                \
            reinterpret_cast<__half2*>(&hbuf16[wid][WR][0])[lane] =               \
                __floats2half2_rn(h0, h1);                                        \
            pbuf[wid][s * 33 + lane] = fmaf(h1, wfb, h0 * wfa);                   \
            cbar();                                                               \
        }

#pragma unroll 1
        for (int s2 = 0; s2 < 16; s2++) {
            STEP(2 * s2,     0, 1)
            STEP(2 * s2 + 1, 1, 0)
        }
#undef STEP

        cbar();
        // transpose-reduce fc partials: lane l produces dot for step s=l of this chunk
        {
            const float* pr = &pbuf[wid][lane * 33];
            float v[32];
#pragma unroll
            for (int j = 0; j < 32; j++) v[j] = pr[j];
#pragma unroll
            for (int st = 16; st >= 1; st >>= 1)
#pragma unroll
                for (int j = 0; j < 32; j++)
                    if (j < st) v[j] = v[j] + v[j + st];
            int tt = dir ? (tb - lane) : (tb + lane);
            g_dot[dir * (BB * TT) + b * TT + tt] = v[0];
        }
        xcur = xnext;
    }

    // final hidden state h_n[dir][b][2l], h_n[dir][b][2l+1] (full fp32 values)
    reinterpret_cast<float2*>(out + BB * TT + dir * (BB * HH) + b * HH)[lane] =
        make_float2(h0, h1);
}

__global__ void birnn_combine(const float* __restrict__ b_fc, float* __restrict__ out)
{
    int i = blockIdx.x * blockDim.x + threadIdx.x;  // 0 .. B*T/4-1
    const float4* df = reinterpret_cast<const float4*>(g_dot);
    const float4* db = reinterpret_cast<const float4*>(g_dot + BB * TT);
    float4 f = df[i], g = db[i];
    float bias = b_fc[0];
    float4 o;
    {
        float z, e, r;
        z = 0.5f * (f.x + g.x) + bias;
        asm("ex2.approx.f32 %0, %1;" : "=f"(e) : "f"(-1.4426950408889634f * z));
        asm("rcp.approx.f32 %0, %1;" : "=f"(r) : "f"(1.0f + e));
        o.x = r;
        z = 0.5f * (f.y + g.y) + bias;
        asm("ex2.approx.f32 %0, %1;" : "=f"(e) : "f"(-1.4426950408889634f * z));
        asm("rcp.approx.f32 %0, %1;" : "=f"(r) : "f"(1.0f + e));
        o.y = r;
        z = 0.5f * (f.z + g.z) + bias;
        asm("ex2.approx.f32 %0, %1;" : "=f"(e) : "f"(-1.4426950408889634f * z));
        asm("rcp.approx.f32 %0, %1;" : "=f"(r) : "f"(1.0f + e));
        o.z = r;
        z = 0.5f * (f.w + g.w) + bias;
        asm("ex2.approx.f32 %0, %1;" : "=f"(e) : "f"(-1.4426950408889634f * z));
        asm("rcp.approx.f32 %0, %1;" : "=f"(r) : "f"(1.0f + e));
        o.w = r;
    }
    reinterpret_cast<float4*>(out)[i] = o;
}

extern "C" void kernel_launch(void* const* d_in, const int* in_sizes, int n_in,
                              void* d_out, int out_size)
{
    const float* x      = (const float*)d_in[0];
    const float* w_ih_f = (const float*)d_in[1];
    const float* w_hh_f = (const float*)d_in[2];
    const float* b_ih_f = (const float*)d_in[3];
    const float* b_hh_f = (const float*)d_in[4];
    const float* w_ih_b = (const float*)d_in[5];
    const float* w_hh_b = (const float*)d_in[6];
    const float* b_ih_b = (const float*)d_in[7];
    const float* b_hh_b = (const float*)d_in[8];
    const float* w_fc   = (const float*)d_in[9];
    const float* b_fc   = (const float*)d_in[10];
    float* out = (float*)d_out;

    birnn_main<<<128, 128>>>(x, w_ih_f, w_hh_f, b_ih_f, b_hh_f,
                             w_ih_b, w_hh_b, b_ih_b, b_hh_b, w_fc, out);
    birnn_combine<<<(BB * TT) / 4 / 256, 256>>>(b_fc, out);
}

// round 17
// speedup vs baseline: 1.0420x; 1.0420x over previous
#include <cuda_runtime.h>
#include <cuda_fp16.h>

#define BB 256
#define TT 2048
#define HH 64
#define NCHUNK (TT / 32)

// scratch for per-(dir,b,t) fc dot products: 4 MB
__device__ float g_dot[2 * BB * TT];

typedef unsigned long long ull;

__device__ __forceinline__ ull pack2(float lo, float hi) {
    ull r; asm("mov.b64 %0, {%1, %2};" : "=l"(r) : "f"(lo), "f"(hi)); return r;
}
__device__ __forceinline__ void unpack2(ull v, float& lo, float& hi) {
    asm("mov.b64 {%0, %1}, %2;" : "=f"(lo), "=f"(hi) : "l"(v));
}
__device__ __forceinline__ ull fma2(ull a, ull b, ull c) {
    ull d; asm("fma.rn.f32x2 %0, %1, %2, %3;" : "=l"(d) : "l"(a), "l"(b), "l"(c)); return d;
}
__device__ __forceinline__ ull add2(ull a, ull b) {
    ull d; asm("add.rn.f32x2 %0, %1, %2;" : "=l"(d) : "l"(a), "l"(b)); return d;
}
__device__ __forceinline__ float tanh_fast(float z) {
    float r; asm("tanh.approx.f32 %0, %1;" : "=f"(r) : "f"(z)); return r;
}
__device__ __forceinline__ __half2 u2h2(unsigned int u) {
    return *reinterpret_cast<__half2*>(&u);
}
// compiler-only ordering fence
__device__ __forceinline__ void cbar() { asm volatile("" ::: "memory"); }

__global__ __launch_bounds__(128, 1) void birnn_main(
    const float* __restrict__ x,
    const float* __restrict__ w_ih_f, const float* __restrict__ w_hh_f,
    const float* __restrict__ b_ih_f, const float* __restrict__ b_hh_f,
    const float* __restrict__ w_ih_b, const float* __restrict__ w_hh_b,
    const float* __restrict__ b_ih_b, const float* __restrict__ b_hh_b,
    const float* __restrict__ w_fc,
    float* __restrict__ out)
{
    // double-buffered h: BOTH buffers hold all 64 rows (branchless dual-store).
    // Consumers read fp32 part from rows 0..15, fp16 part from rows 16..63.
    __shared__ __align__(16) float  hbuf32[4][2][HH];
    __shared__ __align__(16) __half hbuf16[4][2][HH];
    __shared__ float pbuf[4][32 * 33];   // per-warp fc-dot partials (padded)

    const int wid  = threadIdx.x >> 5;
    const int lane = threadIdx.x & 31;
    const int chain = blockIdx.x * 4 + wid;   // 0..511
    const int dir = chain >> 8;               // 0 = fwd, 1 = bwd
    const int b   = chain & 255;

    const float* wih = dir ? w_ih_b : w_ih_f;
    const float* whh = dir ? w_hh_b : w_hh_f;
    const float* bih = dir ? b_ih_b : b_ih_f;
    const float* bhh = dir ? b_hh_b : b_hh_f;

    const int r0 = 2 * lane, r1 = 2 * lane + 1;   // rows owned by this thread

    // --- recurrent weights, k-split 16/48 (same arithmetic as R12) ---
    // fp32 part (k = 0..15), k-paired f32x2
    ull wa32[8], wb32[8];
    // fp16 part (k = 16..63), k-paired half2
    __half2 wa16[24], wb16[24];
    {
        const float* rowA = whh + r0 * HH;
        const float* rowB = whh + r1 * HH;
        const ull* rowAu = reinterpret_cast<const ull*>(rowA);
        const ull* rowBu = reinterpret_cast<const ull*>(rowB);
#pragma unroll
        for (int m = 0; m < 8; m++) { wa32[m] = rowAu[m]; wb32[m] = rowBu[m]; }
#pragma unroll
        for (int m = 0; m < 24; m++) {
            wa16[m] = __floats2half2_rn(rowA[16 + 2 * m], rowA[17 + 2 * m]);
            wb16[m] = __floats2half2_rn(rowB[16 + 2 * m], rowB[17 + 2 * m]);
        }
    }
    const float wihA = wih[r0], wihB = wih[r1];
    const float biasA = bih[r0] + bhh[r0], biasB = bih[r1] + bhh[r1];
    const float wfa = w_fc[r0], wfb = w_fc[r1];

    // h = 0 into phase 0 (all lanes, both buffers, no divergence)
    reinterpret_cast<float2*>(&hbuf32[wid][0][0])[lane] = make_float2(0.f, 0.f);
    reinterpret_cast<unsigned int*>(&hbuf16[wid][0][0])[lane] = 0u;
    cbar();

    float h0 = 0.f, h1 = 0.f;
    const float* xb = x + b * TT;
    const __half2 z16 = __floats2half2_rn(0.f, 0.f);

    // prefetch x for chunk 0
    float xcur = xb[dir ? (TT - 32 + lane) : lane];

    for (int chunk = 0; chunk < NCHUNK; chunk++) {
        const int tb = dir ? (TT - 1 - chunk * 32) : (chunk * 32);
        int nc = (chunk + 1 < NCHUNK) ? (chunk + 1) : chunk;
        float xnext = xb[dir ? (TT - 1 - nc * 32 - 31 + lane) : (nc * 32 + lane)];

#define STEP(SS, RD, WR)                                                          \
        {                                                                         \
            const int s = (SS);                                                   \
            float xs = __shfl_sync(0xffffffffu, xcur, dir ? (31 - s) : s);        \
            const ulonglong2* h32 =                                               \
                reinterpret_cast<const ulonglong2*>(&hbuf32[wid][RD][0]);         \
            const uint4* h16 =                                                    \
                reinterpret_cast<const uint4*>(&hbuf16[wid][RD][16]);             \
            /* HOIST ALL h LOADS to the step top: the fp16 LDS must issue     */  \
            /* BEFORE the fp32 MAC block so its 29-cyc latency drains under   */  \
            /* the fp32 issue stream instead of stalling the fp16 block.      */  \
            ulonglong2 v32a = h32[0];     /* floats 0..3   -> k-pairs 0,1 */      \
            ulonglong2 v32b = h32[1];     /* floats 4..7   -> k-pairs 2,3 */      \
            ulonglong2 v32c = h32[2];     /* floats 8..11  -> k-pairs 4,5 */      \
            ulonglong2 v32d = h32[3];     /* floats 12..15 -> k-pairs 6,7 */      \
            uint4 v16a = h16[0], v16b = h16[1], v16c = h16[2];                    \
            uint4 v16d = h16[3], v16e = h16[4], v16f = h16[5];                    \
            /* init folded into fp32 accumulator lane 0 */                        \
            ull a0 = pack2(fmaf(xs, wihA, biasA), 0.f);                           \
            ull c0 = pack2(fmaf(xs, wihB, biasB), 0.f);                           \
            ull a1 = 0, c1 = 0;                                                   \
            __half2 p0A = z16, p1A = z16, p0B = z16, p1B = z16;                   \
            /* fp32 MAC block (16 fma2) */                                        \
            a0 = fma2(wa32[0], v32a.x, a0);  c0 = fma2(wb32[0], v32a.x, c0);      \
            a1 = fma2(wa32[1], v32a.y, a1);  c1 = fma2(wb32[1], v32a.y, c1);      \
            a0 = fma2(wa32[2], v32b.x, a0);  c0 = fma2(wb32[2], v32b.x, c0);      \
            a1 = fma2(wa32[3], v32b.y, a1);  c1 = fma2(wb32[3], v32b.y, c1);      \
            a0 = fma2(wa32[4], v32c.x, a0);  c0 = fma2(wb32[4], v32c.x, c0);      \
            a1 = fma2(wa32[5], v32c.y, a1);  c1 = fma2(wb32[5], v32c.y, c1);      \
            a0 = fma2(wa32[6], v32d.x, a0);  c0 = fma2(wb32[6], v32d.x, c0);      \
            a1 = fma2(wa32[7], v32d.y, a1);  c1 = fma2(wb32[7], v32d.y, c1);      \
            /* fp16 MAC block (48 HFMA2), operands already resident */            \
            {                                                                     \
                __half2 q0 = u2h2(v16a.x), q1 = u2h2(v16a.y);                     \
                __half2 q2 = u2h2(v16a.z), q3 = u2h2(v16a.w);                     \
                p0A = __hfma2(wa16[0], q0, p0A);  p0B = __hfma2(wb16[0], q0, p0B);\
                p1A = __hfma2(wa16[1], q1, p1A);  p1B = __hfma2(wb16[1], q1, p1B);\
                p0A = __hfma2(wa16[2], q2, p0A);  p0B = __hfma2(wb16[2], q2, p0B);\
                p1A = __hfma2(wa16[3], q3, p1A);  p1B = __hfma2(wb16[3], q3, p1B);\
                q0 = u2h2(v16b.x); q1 = u2h2(v16b.y);                             \
                q2 = u2h2(v16b.z); q3 = u2h2(v16b.w);                             \
                p0A = __hfma2(wa16[4], q0, p0A);  p0B = __hfma2(wb16[4], q0, p0B);\
                p1A = __hfma2(wa16[5], q1, p1A);  p1B = __hfma2(wb16[5], q1, p1B);\
                p0A = __hfma2(wa16[6], q2, p0A);  p0B = __hfma2(wb16[6], q2, p0B);\
                p1A = __hfma2(wa16[7], q3, p1A);  p1B = __hfma2(wb16[7], q3, p1B);\
                q0 = u2h2(v16c.x); q1 = u2h2(v16c.y);                             \
                q2 = u2h2(v16c.z); q3 = u2h2(v16c.w);                             \
                p0A = __hfma2(wa16[8], q0, p0A);  p0B = __hfma2(wb16[8], q0, p0B);\
                p1A = __hfma2(wa16[9], q1, p1A);  p1B = __hfma2(wb16[9], q1, p1B);\
                p0A = __hfma2(wa16[10], q2, p0A); p0B = __hfma2(wb16[10], q2, p0B);\
                p1A = __hfma2(wa16[11], q3, p1A); p1B = __hfma2(wb16[11], q3, p1B);\
                q0 = u2h2(v16d.x); q1 = u2h2(v16d.y);                             \
                q2 = u2h2(v16d.z); q3 = u2h2(v16d.w);                             \
                p0A = __hfma2(wa16[12], q0, p0A); p0B = __hfma2(wb16[12], q0, p0B);\
                p1A = __hfma2(wa16[13], q1, p1A); p1B = __hfma2(wb16[13], q1, p1B);\
                p0A = __hfma2(wa16[14], q2, p0A); p0B = __hfma2(wb16[14], q2, p0B);\
                p1A = __hfma2(wa16[15], q3, p1A); p1B = __hfma2(wb16[15], q3, p1B);\
                q0 = u2h2(v16e.x); q1 = u2h2(v16e.y);                             \
                q2 = u2h2(v16e.z); q3 = u2h2(v16e.w);                             \
                p0A = __hfma2(wa16[16], q0, p0A); p0B = __hfma2(wb16[16], q0, p0B);\
                p1A = __hfma2(wa16[17], q1, p1A); p1B = __hfma2(wb16[17], q1, p1B);\
                p0A = __hfma2(wa16[18], q2, p0A); p0B = __hfma2(wb16[18], q2, p0B);\
                p1A = __hfma2(wa16[19], q3, p1A); p1B = __hfma2(wb16[19], q3, p1B);\
                q0 = u2h2(v16f.x); q1 = u2h2(v16f.y);                             \
                q2 = u2h2(v16f.z); q3 = u2h2(v16f.w);                             \
                p0A = __hfma2(wa16[20], q0, p0A); p0B = __hfma2(wb16[20], q0, p0B);\
                p1A = __hfma2(wa16[21], q1, p1A); p1B = __hfma2(wb16[21], q1, p1B);\
                p0A = __hfma2(wa16[22], q2, p0A); p0B = __hfma2(wb16[22], q2, p0B);\
                p1A = __hfma2(wa16[23], q3, p1A); p1B = __hfma2(wb16[23], q3, p1B);\
            }                                                                     \
            /* fp16 partials -> fp32 BEFORE any full-magnitude add */             \
            float2 qA = __half22float2(__hadd2(p0A, p1A));                        \
            float2 qB = __half22float2(__hadd2(p0B, p1B));                        \
            ull sA = add2(a0, a1);                                                \
            ull sB = add2(c0, c1);                                                \
            float lA, hA, lB, hB;                                                 \
            unpack2(sA, lA, hA);                                                  \
            unpack2(sB, lB, hB);                                                  \
            h0 = tanh_fast((lA + hA) + (qA.x + qA.y));                            \
            h1 = tanh_fast((lB + hB) + (qB.x + qB.y));                            \
            /* branchless dual store: every lane writes both formats */           \
            reinterpret_cast<float2*>(&hbuf32[wid][WR][0])[lane] =                \
                make_float2(h0, h1);                                              \
            reinterpret_cast<__half2*>(&hbuf16[wid][WR][0])[lane] =               \
                __floats2half2_rn(h0, h1);                                        \
            pbuf[wid][s * 33 + lane] = fmaf(h1, wfb, h0 * wfa);                   \
            cbar();                                                               \
        }

#pragma unroll 1
        for (int s2 = 0; s2 < 16; s2++) {
            STEP(2 * s2,     0, 1)
            STEP(2 * s2 + 1, 1, 0)
        }
#undef STEP

        cbar();
        // transpose-reduce fc partials: lane l produces dot for step s=l of this chunk
        {
            const float* pr = &pbuf[wid][lane * 33];
            float v[32];
#pragma unroll
            for (int j = 0; j < 32; j++) v[j] = pr[j];
#pragma unroll
            for (int st = 16; st >= 1; st >>= 1)
#pragma unroll
                for (int j = 0; j < 32; j++)
                    if (j < st) v[j] = v[j] + v[j + st];
            int tt = dir ? (tb - lane) : (tb + lane);
            g_dot[dir * (BB * TT) + b * TT + tt] = v[0];
        }
        xcur = xnext;
    }

    // final hidden state h_n[dir][b][2l], h_n[dir][b][2l+1] (full fp32 values)
    reinterpret_cast<float2*>(out + BB * TT + dir * (BB * HH) + b * HH)[lane] =
        make_float2(h0, h1);
}

__global__ void birnn_combine(const float* __restrict__ b_fc, float* __restrict__ out)
{
    int i = blockIdx.x * blockDim.x + threadIdx.x;  // 0 .. B*T/4-1
    const float4* df = reinterpret_cast<const float4*>(g_dot);
    const float4* db = reinterpret_cast<const float4*>(g_dot + BB * TT);
    float4 f = df[i], g = db[i];
    float bias = b_fc[0];
    float4 o;
    {
        float z, e, r;
        z = 0.5f * (f.x + g.x) + bias;
        asm("ex2.approx.f32 %0, %1;" : "=f"(e) : "f"(-1.4426950408889634f * z));
        asm("rcp.approx.f32 %0, %1;" : "=f"(r) : "f"(1.0f + e));
        o.x = r;
        z = 0.5f * (f.y + g.y) + bias;
        asm("ex2.approx.f32 %0, %1;" : "=f"(e) : "f"(-1.4426950408889634f * z));
        asm("rcp.approx.f32 %0, %1;" : "=f"(r) : "f"(1.0f + e));
        o.y = r;
        z = 0.5f * (f.z + g.z) + bias;
        asm("ex2.approx.f32 %0, %1;" : "=f"(e) : "f"(-1.4426950408889634f * z));
        asm("rcp.approx.f32 %0, %1;" : "=f"(r) : "f"(1.0f + e));
        o.z = r;
        z = 0.5f * (f.w + g.w) + bias;
        asm("ex2.approx.f32 %0, %1;" : "=f"(e) : "f"(-1.4426950408889634f * z));
        asm("rcp.approx.f32 %0, %1;" : "=f"(r) : "f"(1.0f + e));
        o.w = r;
    }
    reinterpret_cast<float4*>(out)[i] = o;
}

extern "C" void kernel_launch(void* const* d_in, const int* in_sizes, int n_in,
                              void* d_out, int out_size)
{
    const float* x      = (const float*)d_in[0];
    const float* w_ih_f = (const float*)d_in[1];
    const float* w_hh_f = (const float*)d_in[2];
    const float* b_ih_f = (const float*)d_in[3];
    const float* b_hh_f = (const float*)d_in[4];
    const float* w_ih_b = (const float*)d_in[5];
    const float* w_hh_b = (const float*)d_in[6];
    const float* b_ih_b = (const float*)d_in[7];
    const float* b_hh_b = (const float*)d_in[8];
    const float* w_fc   = (const float*)d_in[9];
    const float* b_fc   = (const float*)d_in[10];
    float* out = (float*)d_out;

    birnn_main<<<128, 128>>>(x, w_ih_f, w_hh_f, b_ih_f, b_hh_f,
                             w_ih_b, w_hh_b, b_ih_b, b_hh_b, w_fc, out);
    birnn_combine<<<(BB * TT) / 4 / 256, 256>>>(b_fc, out);
}